// round 11
// baseline (speedup 1.0000x reference)
#include <cuda_runtime.h>
#include <cuda_fp16.h>
#include <cstdint>
#include <cstddef>

#define DI __device__ __forceinline__

// ---------------- problem constants ----------------
constexpr int BATCH = 8, CH = 512, TT = 4096, PAD = 8, TP = TT + 2 * PAD;
constexpr int WELEM = CH * CH * 3;        // weights per conv
constexpr int WROW  = 3 * CH;             // 1536 (K per output row)
constexpr int TM    = 128;                // CTA M tile (channels out)
constexpr int TN    = 256;                // CTA N tile (tokens)
constexpr int KC    = 64;                 // K chunk (fp16 elems, per tap)
constexpr int NCHK  = 8;                  // 512/64 ci chunks
constexpr int ROWSB = TN + 16;            // 272 B rows (shift margin 8 each side)
constexpr int NTHR  = 256;                // 8 warps, warp tile 64x64
// stage layout (fp16): A[3 taps][128][64] | B[272][64]
constexpr int A_OFF  = 0;                 // 49152 bytes
constexpr int B_OFF  = 49152;             // 34816 bytes
constexpr int STAGE  = 83968;
constexpr int SMEM_SZ = 2 * STAGE;        // 167936
constexpr int ESW    = 132;               // epilogue smem row pitch (floats)

// ---------------- static device scratch ----------------
__device__ __align__(256) float  g_r[(size_t)BATCH * TT * CH];
__device__ __align__(256) __half g_x[(size_t)BATCH * TP * CH];   // pads stay zero
__device__ __align__(256) __half g_h[(size_t)BATCH * TP * CH];
__device__ __align__(256) __half g_wq[6][(size_t)CH * WROW];
__device__ float g_s[6];
__device__ float g_a[3 * CH];
__device__ float g_binv[3 * CH];

// ---------------- PTX helpers (sm_80-class only) ----------------
DI uint32_t smem_u32(const void* p) {
    uint32_t a;
    asm("{ .reg .u64 t; cvta.to.shared.u64 t, %1; cvt.u32.u64 %0, t; }" : "=r"(a) : "l"(p));
    return a;
}
DI uint32_t swz(uint32_t o) { return o ^ ((o >> 3) & 0x70); }

DI void cp16(uint32_t dst, const void* src) {
    asm volatile("cp.async.cg.shared.global [%0], [%1], 16;" :: "r"(dst), "l"(src) : "memory");
}
DI void cp_commit() { asm volatile("cp.async.commit_group;" ::: "memory"); }
template <int N> DI void cp_wait() { asm volatile("cp.async.wait_group %0;" :: "n"(N) : "memory"); }

DI void ldm4(uint32_t* r, uint32_t addr) {
    asm volatile("ldmatrix.sync.aligned.m8n8.x4.shared.b16 {%0,%1,%2,%3}, [%4];"
                 : "=r"(r[0]), "=r"(r[1]), "=r"(r[2]), "=r"(r[3]) : "r"(addr));
}
DI void mma_f16(float* c, const uint32_t* a, const uint32_t* b) {
    asm volatile(
        "mma.sync.aligned.m16n8k16.row.col.f32.f16.f16.f32 "
        "{%0,%1,%2,%3}, {%4,%5,%6,%7}, {%8,%9}, {%0,%1,%2,%3};"
        : "+f"(c[0]), "+f"(c[1]), "+f"(c[2]), "+f"(c[3])
        : "r"(a[0]), "r"(a[1]), "r"(a[2]), "r"(a[3]), "r"(b[0]), "r"(b[1]));
}

DI uint32_t pack2h(float a, float b) {
    __half2 h = __floats2half2_rn(a, b);
    return *(uint32_t*)&h;
}

// ---------------- prep kernels ----------------
__global__ void k_prep(const float* __restrict__ x) {
    __shared__ float tile[32][33];
    int b = blockIdx.z, c0 = blockIdx.y * 32, t0 = blockIdx.x * 32;
    int tx = threadIdx.x;
    for (int i = threadIdx.y; i < 32; i += 8)
        tile[i][tx] = x[((size_t)b * CH + c0 + i) * TT + t0 + tx];
    __syncthreads();
    for (int i = threadIdx.y; i < 32; i += 8) {
        float v = tile[tx][i];
        g_r[((size_t)b * TT + t0 + i) * CH + c0 + tx] = v;
        g_x[((size_t)b * TP + PAD + t0 + i) * CH + c0 + tx] = __float2half(v);
    }
}

// per-conv absmean (fp64 deterministic, 4-way ILP)
__global__ void k_scale(const float* __restrict__ w1, const float* __restrict__ w2) {
    int conv = blockIdx.x;
    const float* w = ((conv & 1) ? w2 : w1) + (size_t)(conv >> 1) * WELEM;
    double a0 = 0, a1 = 0, a2 = 0, a3 = 0;
    for (int i = threadIdx.x * 4; i < WELEM; i += 4096) {
        a0 += (double)fabsf(w[i]);
        a1 += (double)fabsf(w[i + 1]);
        a2 += (double)fabsf(w[i + 2]);
        a3 += (double)fabsf(w[i + 3]);
    }
    __shared__ double sm[1024];
    sm[threadIdx.x] = (a0 + a1) + (a2 + a3);
    __syncthreads();
    for (int s = 512; s > 0; s >>= 1) {
        if (threadIdx.x < s) sm[threadIdx.x] += sm[threadIdx.x + s];
        __syncthreads();
    }
    if (threadIdx.x == 0) g_s[conv] = (float)(sm[0] / (double)WELEM);
}

// quantize weights to ternary fp16 [co][tap][ci] + snake param precompute
__global__ void k_qa(const float* __restrict__ w1, const float* __restrict__ w2,
                     const float* __restrict__ alpha, const float* __restrict__ beta) {
    if (blockIdx.x >= 18432) {
        int i = (blockIdx.x - 18432) * 256 + threadIdx.x;
        if (i < 3 * CH) {
            g_a[i] = expf(alpha[i]);
            g_binv[i] = 1.f / (expf(beta[i]) + 1e-9f);
        }
        return;
    }
    size_t idx = (size_t)blockIdx.x * 256 + threadIdx.x;
    int conv = (int)(idx / WELEM);
    int e = (int)(idx - (size_t)conv * WELEM);
    int co = e / WROW;
    int rem = e - co * WROW;
    int k = rem >> 9, ci = rem & 511;                 // dst layout [co][tap][ci]
    const float* w = ((conv & 1) ? w2 : w1) + (size_t)(conv >> 1) * WELEM;
    float s = g_s[conv] + 1e-5f;
    float q = rintf(w[(size_t)co * WROW + ci * 3 + k] / s); // src layout [co][ci][k]
    q = fminf(1.f, fmaxf(-1.f, q));
    g_wq[conv][e] = __float2half(q);
}

__global__ void k_out(float* __restrict__ out) {
    __shared__ float tile[32][33];
    int b = blockIdx.z, c0 = blockIdx.y * 32, t0 = blockIdx.x * 32;
    int tx = threadIdx.x;
    for (int i = threadIdx.y; i < 32; i += 8)
        tile[i][tx] = g_r[((size_t)b * TT + t0 + i) * CH + c0 + tx];
    __syncthreads();
    for (int i = threadIdx.y; i < 32; i += 8)
        out[((size_t)b * CH + c0 + i) * TT + t0 + tx] = tile[tx][i];
}

// ---------------- GEMM chunk loader (256 threads) ----------------
// Chunk c: ci0=c*64, all 3 taps of A, B rows [t0-8, t0+264) padded space.
DI void load_chunk(int c, int tid, uint32_t sb, int m0, int b, int t0,
                   const __half* __restrict__ X, const __half* __restrict__ W) {
    int ci0 = c * KC;
    uint32_t st = sb + (c & 1) * STAGE;
    const __half* As = W + (size_t)m0 * WROW + ci0;
    size_t bbase = ((size_t)b * TP + t0) * CH + ci0;   // padded row t0 == token t0-8
#pragma unroll
    for (int jj = 0; jj < 12; jj++) {                  // A: 3*128*8 = 3072 cp16
        int idx = tid + NTHR * jj;
        int tap = idx >> 10, e = idx & 1023;
        int row = e >> 3, c16 = e & 7;
        uint32_t so = swz((uint32_t)(row * 128 + c16 * 16));
        cp16(st + A_OFF + tap * 16384 + so,
             (const char*)(As + (size_t)row * WROW + tap * CH) + c16 * 16);
    }
#pragma unroll
    for (int jj = 0; jj < 9; jj++) {                   // B: 272*8 = 2176 cp16
        int idx = tid + NTHR * jj;
        if (idx < ROWSB * 8) {
            int row = idx >> 3, c16 = idx & 7;
            uint32_t so = swz((uint32_t)(row * 128 + c16 * 16));
            cp16(st + B_OFF + so, (const char*)(X + bbase + (size_t)row * CH) + c16 * 16);
        }
    }
    cp_commit();
}

// ---------------- main GEMM kernel ----------------
// MODE 0: conv1 -> snake -> g_h fp16
// MODE 1: conv2 -> g_r += v, g_x fp16 for next block
// MODE 2: conv2 final -> g_r += v only
template <int DIL, int MODE>
__global__ void __launch_bounds__(NTHR, 1)
gemm_k(int conv, const float* __restrict__ bias) {
    extern __shared__ char smem[];
    uint32_t sb = smem_u32(smem);
    int tid = threadIdx.x;
    int wid = tid >> 5, lane = tid & 31;
    int wm = wid >> 2, wn = wid & 3;       // warp grid 2m x 4n (64co x 64tok per warp)
    int m0 = blockIdx.x * TM;
    int nt = blockIdx.y;
    int b = nt >> 4, t0 = (nt & 15) * TN;
    const __half* X = (MODE == 0) ? g_x : g_h;
    const __half* W = g_wq[conv];

    float acc[4][8][4];
#pragma unroll
    for (int i = 0; i < 4; i++)
#pragma unroll
        for (int j = 0; j < 8; j++)
#pragma unroll
            for (int r = 0; r < 4; r++) acc[i][j][r] = 0.f;

    // ldmatrix lane roles (b16 element offsets)
    int lsel = lane >> 3, l7 = lane & 7;
    int a_row = (lsel & 1) * 8 + l7, a_kc = (lsel >> 1) * 8;   // A: m8 pair, k8 pair
    int b_row = (lsel >> 1) * 8 + l7, b_kc = (lsel & 1) * 8;   // B: n8 pair, k8 pair

    load_chunk(0, tid, sb, m0, b, t0, X, W);
#pragma unroll 1
    for (int c = 0; c < NCHK; c++) {
        if (c + 1 < NCHK) {
            load_chunk(c + 1, tid, sb, m0, b, t0, X, W);
            cp_wait<1>();
        } else {
            cp_wait<0>();
        }
        __syncthreads();
        uint32_t st = sb + (c & 1) * STAGE;
#pragma unroll 1
        for (int tap = 0; tap < 3; tap++) {            // unroll 1: bound addr-chain regs
            uint32_t ab = st + A_OFF + tap * 16384;
            int rowoff = 8 + (tap - 1) * DIL;          // B smem row for token j is rowoff+j
#pragma unroll
            for (int ks = 0; ks < 4; ks++) {
                uint32_t afr[4][4];
#pragma unroll
                for (int mf = 0; mf < 4; mf++) {
                    uint32_t o = (uint32_t)((wm * 64 + mf * 16 + a_row) * 128 + (ks * 16 + a_kc) * 2);
                    ldm4(afr[mf], ab + swz(o));
                }
#pragma unroll
                for (int h = 0; h < 4; h++) {          // B loaded 1 ldm4 at a time, consumed at once
                    uint32_t o = (uint32_t)((rowoff + wn * 64 + h * 16 + b_row) * 128 +
                                            (ks * 16 + b_kc) * 2);
                    uint32_t r4[4];
                    ldm4(r4, st + B_OFF + swz(o));
#pragma unroll
                    for (int mf = 0; mf < 4; mf++) {
                        mma_f16(acc[mf][2 * h],     afr[mf], r4);
                        mma_f16(acc[mf][2 * h + 1], afr[mf], r4 + 2);
                    }
                }
            }
        }
        __syncthreads();
    }

    // -------- epilogue: two 128-token passes staged through SMEM --------
    const float s = g_s[conv];
    const int blkI = conv >> 1;
    float* es = (float*)smem;
    int g = lane >> 2, tig = lane & 3;
    int rr = tid >> 5;             // 8 token-rows per sweep step
    int cc = (tid & 31) * 4;       // 4 channels per thread
    float4 bi4 = *(const float4*)&bias[m0 + cc];
    float4 a4 = {0, 0, 0, 0}, bv4 = {0, 0, 0, 0};
    if (MODE == 0) {
        a4 = *(const float4*)&g_a[blkI * CH + m0 + cc];
        bv4 = *(const float4*)&g_binv[blkI * CH + m0 + cc];
    }
#pragma unroll 1
    for (int p = 0; p < 2; p++) {
        __syncthreads();
        if ((wn >> 1) == p) {
#pragma unroll
            for (int mf = 0; mf < 4; mf++)
#pragma unroll
                for (int nf = 0; nf < 8; nf++)
#pragma unroll
                    for (int r = 0; r < 4; r++) {
                        int co_l = wm * 64 + mf * 16 + g + (r >> 1) * 8;
                        int t_l = (wn & 1) * 64 + nf * 8 + 2 * tig + (r & 1);
                        es[t_l * ESW + co_l] = acc[mf][nf][r];
                    }
        }
        __syncthreads();
#pragma unroll 1
        for (int it = 0; it < 16; it++) {
            int tr = it * 8 + rr;
            float4 v = *(float4*)&es[tr * ESW + cc];
            v.x = fmaf(s, v.x, bi4.x);
            v.y = fmaf(s, v.y, bi4.y);
            v.z = fmaf(s, v.z, bi4.z);
            v.w = fmaf(s, v.w, bi4.w);
            int t = t0 + p * 128 + tr;
            if (MODE == 0) {
                float sn;
                sn = __sinf(a4.x * v.x); v.x += bv4.x * sn * sn;
                sn = __sinf(a4.y * v.y); v.y += bv4.y * sn * sn;
                sn = __sinf(a4.z * v.z); v.z += bv4.z * sn * sn;
                sn = __sinf(a4.w * v.w); v.w += bv4.w * sn * sn;
                uint2 pk = { pack2h(v.x, v.y), pack2h(v.z, v.w) };
                *(uint2*)&g_h[((size_t)b * TP + PAD + t) * CH + m0 + cc] = pk;
            } else {
                size_t o = ((size_t)b * TT + t) * CH + m0 + cc;
                float4 rv = *(float4*)&g_r[o];
                rv.x += v.x; rv.y += v.y; rv.z += v.z; rv.w += v.w;
                *(float4*)&g_r[o] = rv;
                if (MODE == 1) {
                    uint2 pk = { pack2h(rv.x, rv.y), pack2h(rv.z, rv.w) };
                    *(uint2*)&g_x[((size_t)b * TP + PAD + t) * CH + m0 + cc] = pk;
                }
            }
        }
    }
}

// ---------------- launch ----------------
extern "C" void kernel_launch(void* const* d_in, const int* in_sizes, int n_in,
                              void* d_out, int out_size) {
    const float* x     = (const float*)d_in[0];
    const float* w1    = (const float*)d_in[1];
    const float* b1    = (const float*)d_in[2];
    const float* alpha = (const float*)d_in[3];
    const float* beta  = (const float*)d_in[4];
    const float* w2    = (const float*)d_in[5];
    const float* b2    = (const float*)d_in[6];
    float* out = (float*)d_out;

    cudaFuncSetAttribute(gemm_k<1, 0>, cudaFuncAttributeMaxDynamicSharedMemorySize, SMEM_SZ);
    cudaFuncSetAttribute(gemm_k<1, 1>, cudaFuncAttributeMaxDynamicSharedMemorySize, SMEM_SZ);
    cudaFuncSetAttribute(gemm_k<3, 0>, cudaFuncAttributeMaxDynamicSharedMemorySize, SMEM_SZ);
    cudaFuncSetAttribute(gemm_k<5, 0>, cudaFuncAttributeMaxDynamicSharedMemorySize, SMEM_SZ);
    cudaFuncSetAttribute(gemm_k<1, 2>, cudaFuncAttributeMaxDynamicSharedMemorySize, SMEM_SZ);

    dim3 tb(32, 8), tg(TT / 32, CH / 32, BATCH);
    k_prep<<<tg, tb>>>(x);                         // launch 1
    k_scale<<<6, 1024>>>(w1, w2);                  // launch 2
    k_qa<<<18432 + 6, 256>>>(w1, w2, alpha, beta); // launch 3

    dim3 gg(CH / TM, BATCH * TT / TN);             // (4, 128)
    gemm_k<1, 0><<<gg, NTHR, SMEM_SZ>>>(0, b1);    // launch 4 (ncu capture slot)
    gemm_k<1, 1><<<gg, NTHR, SMEM_SZ>>>(1, b2);
    gemm_k<3, 0><<<gg, NTHR, SMEM_SZ>>>(2, b1 + 512);
    gemm_k<1, 1><<<gg, NTHR, SMEM_SZ>>>(3, b2 + 512);
    gemm_k<5, 0><<<gg, NTHR, SMEM_SZ>>>(4, b1 + 1024);
    gemm_k<1, 2><<<gg, NTHR, SMEM_SZ>>>(5, b2 + 1024);

    k_out<<<tg, tb>>>(out);
}

// round 12
// speedup vs baseline: 1.4043x; 1.4043x over previous
#include <cuda_runtime.h>
#include <cuda_fp16.h>
#include <cstdint>
#include <cstddef>

#define DI __device__ __forceinline__

// ---------------- problem constants ----------------
constexpr int BATCH = 8, CH = 512, TT = 4096, PAD = 8, TP = TT + 2 * PAD;
constexpr int WELEM = CH * CH * 3;        // weights per conv
constexpr int WROW  = 3 * CH;             // 1536 (K per output row)
constexpr int TM    = 128;                // CTA M tile (channels out)
constexpr int TN    = 256;                // CTA N tile (tokens)
constexpr int KC    = 64;                 // K chunk (fp16 elems, per tap)
constexpr int NCHK  = 8;                  // 512/64 ci chunks
constexpr int ROWSB = TN + 16;            // 272 B rows (shift margin 8 each side)
constexpr int NTHR  = 512;                // 16 warps, 4 per SMSP, warp tile 64x32
// stage layout (fp16): A[3 taps][128][64] | B[272][64]
constexpr int A_OFF  = 0;                 // 49152 bytes
constexpr int B_OFF  = 49152;             // 34816 bytes
constexpr int STAGE  = 83968;
constexpr int SMEM_SZ = 2 * STAGE;        // 167936
constexpr int ESW    = 132;               // epilogue smem row pitch (floats), [t][co]
constexpr int ES2_OFF = 69632;            // second epilogue buffer (bytes)
constexpr int P2     = 133;               // transposed pitch (floats), [co][t]

// ---------------- static device scratch ----------------
__device__ __align__(256) float  g_r[(size_t)BATCH * TT * CH];
__device__ __align__(256) __half g_x[(size_t)BATCH * TP * CH];   // pads stay zero
__device__ __align__(256) __half g_h[(size_t)BATCH * TP * CH];
__device__ __align__(256) __half g_wq[6][(size_t)CH * WROW];
__device__ float  g_s[6];
__device__ double g_part[6 * 64];
__device__ float  g_a[3 * CH];
__device__ float  g_binv[3 * CH];

// ---------------- PTX helpers (sm_80-class only) ----------------
DI uint32_t smem_u32(const void* p) {
    uint32_t a;
    asm("{ .reg .u64 t; cvta.to.shared.u64 t, %1; cvt.u32.u64 %0, t; }" : "=r"(a) : "l"(p));
    return a;
}
DI uint32_t swz(uint32_t o) { return o ^ ((o >> 3) & 0x70); }

DI void cp16(uint32_t dst, const void* src) {
    asm volatile("cp.async.cg.shared.global [%0], [%1], 16;" :: "r"(dst), "l"(src) : "memory");
}
DI void cp_commit() { asm volatile("cp.async.commit_group;" ::: "memory"); }
template <int N> DI void cp_wait() { asm volatile("cp.async.wait_group %0;" :: "n"(N) : "memory"); }

DI void ldm4(uint32_t* r, uint32_t addr) {
    asm volatile("ldmatrix.sync.aligned.m8n8.x4.shared.b16 {%0,%1,%2,%3}, [%4];"
                 : "=r"(r[0]), "=r"(r[1]), "=r"(r[2]), "=r"(r[3]) : "r"(addr));
}
DI void mma_f16(float* c, const uint32_t* a, const uint32_t* b) {
    asm volatile(
        "mma.sync.aligned.m16n8k16.row.col.f32.f16.f16.f32 "
        "{%0,%1,%2,%3}, {%4,%5,%6,%7}, {%8,%9}, {%0,%1,%2,%3};"
        : "+f"(c[0]), "+f"(c[1]), "+f"(c[2]), "+f"(c[3])
        : "r"(a[0]), "r"(a[1]), "r"(a[2]), "r"(a[3]), "r"(b[0]), "r"(b[1]));
}

DI uint32_t pack2h(float a, float b) {
    __half2 h = __floats2half2_rn(a, b);
    return *(uint32_t*)&h;
}

// ---------------- prep kernels ----------------
// launch 1: transpose x -> g_r + g_x  AND  absmean partials (384 extra blocks)
__global__ void k_fused(const float* __restrict__ x,
                        const float* __restrict__ w1, const float* __restrict__ w2) {
    if (blockIdx.x < 16384) {
        int bx = blockIdx.x;
        int t0 = (bx & 127) * 32, c0 = ((bx >> 7) & 15) * 32, b = bx >> 11;
        int tx = threadIdx.x & 31, ty = threadIdx.x >> 5;
        __shared__ float tile[32][33];
        for (int i = ty; i < 32; i += 8)
            tile[i][tx] = x[((size_t)b * CH + c0 + i) * TT + t0 + tx];
        __syncthreads();
        for (int i = ty; i < 32; i += 8) {
            float v = tile[tx][i];
            g_r[((size_t)b * TT + t0 + i) * CH + c0 + tx] = v;
            g_x[((size_t)b * TP + PAD + t0 + i) * CH + c0 + tx] = __float2half(v);
        }
    } else {
        int q = blockIdx.x - 16384;      // 0..383
        int conv = q >> 6, part = q & 63;
        const float* w = ((conv & 1) ? w2 : w1) + (size_t)(conv >> 1) * WELEM +
                         part * (WELEM / 64);
        double a0 = 0, a1 = 0, a2 = 0, a3 = 0;
        for (int i = threadIdx.x * 4; i < WELEM / 64; i += 1024) {
            a0 += (double)fabsf(w[i]);
            a1 += (double)fabsf(w[i + 1]);
            a2 += (double)fabsf(w[i + 2]);
            a3 += (double)fabsf(w[i + 3]);
        }
        __shared__ double sm[256];
        sm[threadIdx.x] = (a0 + a1) + (a2 + a3);
        __syncthreads();
        for (int s = 128; s > 0; s >>= 1) {
            if (threadIdx.x < s) sm[threadIdx.x] += sm[threadIdx.x + s];
            __syncthreads();
        }
        if (threadIdx.x == 0) g_part[q] = sm[0];
    }
}

// launch 2: quantize weights (3072 blocks per conv, no conv straddle) + finalize g_s + snake
__global__ void k_qa(const float* __restrict__ w1, const float* __restrict__ w2,
                     const float* __restrict__ alpha, const float* __restrict__ beta) {
    if (blockIdx.x >= 18432) {
        int i = (blockIdx.x - 18432) * 256 + threadIdx.x;
        if (i < 3 * CH) {
            g_a[i] = expf(alpha[i]);
            g_binv[i] = 1.f / (expf(beta[i]) + 1e-9f);
        }
        if (blockIdx.x == 18432 && threadIdx.x < 6) {
            double acc = 0;
            for (int j = 0; j < 64; j++) acc += g_part[threadIdx.x * 64 + j];
            g_s[threadIdx.x] = (float)(acc / (double)WELEM);
        }
        return;
    }
    int conv = blockIdx.x / 3072;
    __shared__ float s_sh;
    if (threadIdx.x == 0) {
        double acc = 0;
        for (int j = 0; j < 64; j++) acc += g_part[conv * 64 + j];
        s_sh = (float)(acc / (double)WELEM) + 1e-5f;
    }
    __syncthreads();
    float s = s_sh;
    size_t idx = (size_t)blockIdx.x * 256 + threadIdx.x;
    int e = (int)(idx - (size_t)conv * WELEM);
    int co = e / WROW;
    int rem = e - co * WROW;
    int k = rem >> 9, ci = rem & 511;                 // dst layout [co][tap][ci]
    const float* w = ((conv & 1) ? w2 : w1) + (size_t)(conv >> 1) * WELEM;
    float q = rintf(w[(size_t)co * WROW + ci * 3 + k] / s); // src layout [co][ci][k]
    q = fminf(1.f, fmaxf(-1.f, q));
    g_wq[conv][e] = __float2half(q);
}

// ---------------- GEMM chunk loader (512 threads) ----------------
DI void load_chunk(int c, int tid, uint32_t sb, int m0, int b, int t0,
                   const __half* __restrict__ X, const __half* __restrict__ W) {
    int ci0 = c * KC;
    uint32_t st = sb + (c & 1) * STAGE;
    const __half* As = W + (size_t)m0 * WROW + ci0;
    size_t bbase = ((size_t)b * TP + t0) * CH + ci0;   // padded row t0 == token t0-8
#pragma unroll
    for (int jj = 0; jj < 6; jj++) {                   // A: 3*128*8 = 3072 cp16
        int idx = tid + NTHR * jj;
        int tap = idx >> 10, e = idx & 1023;
        int row = e >> 3, c16 = e & 7;
        uint32_t so = swz((uint32_t)(row * 128 + c16 * 16));
        cp16(st + A_OFF + tap * 16384 + so,
             (const char*)(As + (size_t)row * WROW + tap * CH) + c16 * 16);
    }
#pragma unroll
    for (int jj = 0; jj < 5; jj++) {                   // B: 272*8 = 2176 cp16
        int idx = tid + NTHR * jj;
        if (idx < ROWSB * 8) {
            int row = idx >> 3, c16 = idx & 7;
            uint32_t so = swz((uint32_t)(row * 128 + c16 * 16));
            cp16(st + B_OFF + so, (const char*)(X + bbase + (size_t)row * CH) + c16 * 16);
        }
    }
    cp_commit();
}

// ---------------- main GEMM kernel ----------------
// MODE 0: conv1 -> snake -> g_h fp16
// MODE 1: conv2 -> g_r += v, g_x fp16 for next block
// MODE 2: conv2 final -> out[b][c][t] directly (fused transpose), g_r untouched
template <int DIL, int MODE>
__global__ void __launch_bounds__(NTHR, 1)
gemm_k(int conv, const float* __restrict__ bias, float* __restrict__ outp) {
    extern __shared__ char smem[];
    uint32_t sb = smem_u32(smem);
    int tid = threadIdx.x;
    int wid = tid >> 5, lane = tid & 31;
    int wm = wid >> 3, wn = wid & 7;       // warp grid 2m x 8n (64co x 32tok per warp)
    int m0 = blockIdx.x * TM;
    int nt = blockIdx.y;
    int b = nt >> 4, t0 = (nt & 15) * TN;
    const __half* X = (MODE == 0) ? g_x : g_h;
    const __half* W = g_wq[conv];

    float acc[4][4][4];
#pragma unroll
    for (int i = 0; i < 4; i++)
#pragma unroll
        for (int j = 0; j < 4; j++)
#pragma unroll
            for (int r = 0; r < 4; r++) acc[i][j][r] = 0.f;

    // ldmatrix lane roles (b16 element offsets)
    int lsel = lane >> 3, l7 = lane & 7;
    int a_row = (lsel & 1) * 8 + l7, a_kc = (lsel >> 1) * 8;   // A: m8 pair, k8 pair
    int b_row = (lsel >> 1) * 8 + l7, b_kc = (lsel & 1) * 8;   // B: n8 pair, k8 pair

    load_chunk(0, tid, sb, m0, b, t0, X, W);
#pragma unroll 1
    for (int c = 0; c < NCHK; c++) {
        if (c + 1 < NCHK) {
            load_chunk(c + 1, tid, sb, m0, b, t0, X, W);
            cp_wait<1>();
        } else {
            cp_wait<0>();
        }
        __syncthreads();
        uint32_t st = sb + (c & 1) * STAGE;
#pragma unroll
        for (int tap = 0; tap < 3; tap++) {
            uint32_t ab = st + A_OFF + tap * 16384;
            int rowoff = 8 + (tap - 1) * DIL;          // B smem row for token j is rowoff+j
#pragma unroll
            for (int ks = 0; ks < 4; ks++) {
                uint32_t afr[4][4];
#pragma unroll
                for (int mf = 0; mf < 4; mf++) {
                    uint32_t o = (uint32_t)((wm * 64 + mf * 16 + a_row) * 128 + (ks * 16 + a_kc) * 2);
                    ldm4(afr[mf], ab + swz(o));
                }
                uint32_t bf[4][2];
#pragma unroll
                for (int h = 0; h < 2; h++) {
                    uint32_t o = (uint32_t)((rowoff + wn * 32 + h * 16 + b_row) * 128 +
                                            (ks * 16 + b_kc) * 2);
                    uint32_t r4[4];
                    ldm4(r4, st + B_OFF + swz(o));
                    bf[2 * h][0] = r4[0]; bf[2 * h][1] = r4[1];
                    bf[2 * h + 1][0] = r4[2]; bf[2 * h + 1][1] = r4[3];
                }
#pragma unroll
                for (int mf = 0; mf < 4; mf++)
#pragma unroll
                    for (int nf = 0; nf < 4; nf++)
                        mma_f16(acc[mf][nf], afr[mf], bf[nf]);
            }
        }
        __syncthreads();
    }

    // -------- epilogue: two 128-token passes staged through SMEM --------
    const float s = g_s[conv];
    const int blkI = conv >> 1;
    float* es  = (float*)smem;
    float* es2 = (float*)(smem + ES2_OFF);
    int g = lane >> 2, tig = lane & 3;
    int rr = tid >> 5;             // 16 token-rows per sweep step
    int cc = (tid & 31) * 4;       // 4 channels per thread
    float4 bi4 = *(const float4*)&bias[m0 + cc];
    float4 a4 = {0, 0, 0, 0}, bv4 = {0, 0, 0, 0};
    if (MODE == 0) {
        a4 = *(const float4*)&g_a[blkI * CH + m0 + cc];
        bv4 = *(const float4*)&g_binv[blkI * CH + m0 + cc];
    }
#pragma unroll 1
    for (int p = 0; p < 2; p++) {
        __syncthreads();
        if ((wn >> 2) == p) {
#pragma unroll
            for (int mf = 0; mf < 4; mf++)
#pragma unroll
                for (int nf = 0; nf < 4; nf++)
#pragma unroll
                    for (int r = 0; r < 4; r++) {
                        int co_l = wm * 64 + mf * 16 + g + (r >> 1) * 8;
                        int t_l = (wn & 3) * 32 + nf * 8 + 2 * tig + (r & 1);
                        es[t_l * ESW + co_l] = acc[mf][nf][r];
                    }
        }
        __syncthreads();
#pragma unroll 1
        for (int it = 0; it < 8; it++) {
            int tr = it * 16 + rr;
            float4 v = *(float4*)&es[tr * ESW + cc];
            v.x = fmaf(s, v.x, bi4.x);
            v.y = fmaf(s, v.y, bi4.y);
            v.z = fmaf(s, v.z, bi4.z);
            v.w = fmaf(s, v.w, bi4.w);
            int t = t0 + p * 128 + tr;
            if (MODE == 0) {
                float sn;
                sn = __sinf(a4.x * v.x); v.x += bv4.x * sn * sn;
                sn = __sinf(a4.y * v.y); v.y += bv4.y * sn * sn;
                sn = __sinf(a4.z * v.z); v.z += bv4.z * sn * sn;
                sn = __sinf(a4.w * v.w); v.w += bv4.w * sn * sn;
                uint2 pk = { pack2h(v.x, v.y), pack2h(v.z, v.w) };
                *(uint2*)&g_h[((size_t)b * TP + PAD + t) * CH + m0 + cc] = pk;
            } else {
                size_t o = ((size_t)b * TT + t) * CH + m0 + cc;
                float4 rv = *(float4*)&g_r[o];
                rv.x += v.x; rv.y += v.y; rv.z += v.z; rv.w += v.w;
                if (MODE == 1) {
                    *(float4*)&g_r[o] = rv;
                    uint2 pk = { pack2h(rv.x, rv.y), pack2h(rv.z, rv.w) };
                    *(uint2*)&g_x[((size_t)b * TP + PAD + t) * CH + m0 + cc] = pk;
                } else {
                    es2[(cc + 0) * P2 + tr] = rv.x;
                    es2[(cc + 1) * P2 + tr] = rv.y;
                    es2[(cc + 2) * P2 + tr] = rv.z;
                    es2[(cc + 3) * P2 + tr] = rv.w;
                }
            }
        }
        if (MODE == 2) {
            __syncthreads();
#pragma unroll
            for (int i = 0; i < 8; i++) {
                int co = wid * 8 + i;
#pragma unroll
                for (int j = 0; j < 4; j++) {
                    int tl = lane + 32 * j;
                    outp[((size_t)b * CH + m0 + co) * TT + t0 + p * 128 + tl] =
                        es2[co * P2 + tl];
                }
            }
        }
    }
}

// ---------------- launch ----------------
extern "C" void kernel_launch(void* const* d_in, const int* in_sizes, int n_in,
                              void* d_out, int out_size) {
    const float* x     = (const float*)d_in[0];
    const float* w1    = (const float*)d_in[1];
    const float* b1    = (const float*)d_in[2];
    const float* alpha = (const float*)d_in[3];
    const float* beta  = (const float*)d_in[4];
    const float* w2    = (const float*)d_in[5];
    const float* b2    = (const float*)d_in[6];
    float* out = (float*)d_out;

    cudaFuncSetAttribute(gemm_k<1, 0>, cudaFuncAttributeMaxDynamicSharedMemorySize, SMEM_SZ);
    cudaFuncSetAttribute(gemm_k<1, 1>, cudaFuncAttributeMaxDynamicSharedMemorySize, SMEM_SZ);
    cudaFuncSetAttribute(gemm_k<3, 0>, cudaFuncAttributeMaxDynamicSharedMemorySize, SMEM_SZ);
    cudaFuncSetAttribute(gemm_k<5, 0>, cudaFuncAttributeMaxDynamicSharedMemorySize, SMEM_SZ);
    cudaFuncSetAttribute(gemm_k<1, 2>, cudaFuncAttributeMaxDynamicSharedMemorySize, SMEM_SZ);

    k_fused<<<16384 + 384, 256>>>(x, w1, w2);            // launch 1
    k_qa<<<18432 + 6, 256>>>(w1, w2, alpha, beta);       // launch 2

    dim3 gg(CH / TM, BATCH * TT / TN);                   // (4, 128)
    gemm_k<1, 0><<<gg, NTHR, SMEM_SZ>>>(0, b1, out);     // launch 3
    gemm_k<1, 1><<<gg, NTHR, SMEM_SZ>>>(1, b2, out);     // launch 4 (ncu capture: MODE 1)
    gemm_k<3, 0><<<gg, NTHR, SMEM_SZ>>>(2, b1 + 512, out);
    gemm_k<1, 1><<<gg, NTHR, SMEM_SZ>>>(3, b2 + 512, out);
    gemm_k<5, 0><<<gg, NTHR, SMEM_SZ>>>(4, b1 + 1024, out);
    gemm_k<1, 2><<<gg, NTHR, SMEM_SZ>>>(5, b2 + 1024, out);
}